// round 2
// baseline (speedup 1.0000x reference)
#include <cuda_runtime.h>
#include <math.h>
#include <stdint.h>

#define Bn   2
#define Sn   4096
#define Dn   512
#define Hn   8
#define DKn  64
#define DFFn 2048
#define Mrows (Bn*Sn)   /* 8192 */

// ---------------- scratch (no allocs allowed) ----------------
__device__ float g_q[Bn*Hn*Sn*DKn];     // [B,H,S,DK]
__device__ float g_k[Bn*Hn*Sn*DKn];
__device__ float g_v[Bn*Hn*Sn*DKn];
__device__ float g_ctx[Mrows*Dn];       // [B,S,D]
__device__ float g_res1[Mrows*Dn];      // x + attn_out  (reused for res2)
__device__ float g_x1[Mrows*Dn];        // LN1 output
__device__ float g_ff[Mrows*DFFn];      // relu(x1@w1+b1)

// ---------------- GEMM: C[M,N] = A[M,K] @ W[K,N] + epilogue ----------------
// 64x64 block tile, BK=32, 256 threads, 4x4 per-thread microtile.
#define EPI_QKV       0
#define EPI_RES       1
#define EPI_BIAS_RELU 2
#define EPI_BIAS_RES  3

template<int N, int K, int EPI>
__global__ __launch_bounds__(256)
void gemm_kernel(const float* __restrict__ A, const float* __restrict__ W,
                 const float* __restrict__ bias, const float* __restrict__ res,
                 float* __restrict__ out)
{
    __shared__ float As[32][65];
    __shared__ float Bs[32][65];
    const int tid = threadIdx.x;
    const int tx = tid & 15, ty = tid >> 4;
    const int row0 = blockIdx.y * 64;
    const int col0 = blockIdx.x * 64;

    float acc[4][4] = {};

    for (int k0 = 0; k0 < K; k0 += 32) {
        #pragma unroll
        for (int i = tid; i < 64*32; i += 256) {
            int kk = i & 31, m = i >> 5;
            As[kk][m] = A[(size_t)(row0 + m) * K + k0 + kk];
        }
        #pragma unroll
        for (int i = tid; i < 32*64; i += 256) {
            int n = i & 63, kk = i >> 6;
            Bs[kk][n] = W[(size_t)(k0 + kk) * N + col0 + n];
        }
        __syncthreads();
        #pragma unroll
        for (int kk = 0; kk < 32; kk++) {
            float a[4], b[4];
            #pragma unroll
            for (int i = 0; i < 4; i++) a[i] = As[kk][ty*4 + i];
            #pragma unroll
            for (int j = 0; j < 4; j++) b[j] = Bs[kk][tx*4 + j];
            #pragma unroll
            for (int i = 0; i < 4; i++)
                #pragma unroll
                for (int j = 0; j < 4; j++)
                    acc[i][j] = fmaf(a[i], b[j], acc[i][j]);
        }
        __syncthreads();
    }

    #pragma unroll
    for (int i = 0; i < 4; i++) {
        const int r = row0 + ty*4 + i;
        #pragma unroll
        for (int j = 0; j < 4; j++) {
            const int c = col0 + tx*4 + j;
            float v = acc[i][j];
            if (EPI == EPI_QKV) {
                // row r = b*S + s ; col c = h*DK + dk ; out layout [B,H,S,DK]
                int b = r / Sn, s = r - b * Sn;
                int h = c >> 6, dk = c & 63;
                out[(((size_t)b * Hn + h) * Sn + s) * DKn + dk] = v;
            } else if (EPI == EPI_RES) {
                out[(size_t)r * N + c] = v + res[(size_t)r * N + c];
            } else if (EPI == EPI_BIAS_RELU) {
                v += bias[c];
                out[(size_t)r * N + c] = v > 0.f ? v : 0.f;
            } else { // EPI_BIAS_RES
                out[(size_t)r * N + c] = v + bias[c] + res[(size_t)r * N + c];
            }
        }
    }
}

// ---------------- Flash attention (fp32, online softmax) ----------------
// grid (S/64, H, B), 256 threads. Tiles: Q 64x64, K 64x64, V 64x64, P 64x64.
__global__ __launch_bounds__(256)
void attn_kernel(const int* __restrict__ mask)
{
    extern __shared__ float sm[];
    float* Qs = sm;                 // 64*65
    float* Ks = Qs + 64*65;
    float* Vs = Ks + 64*65;
    float* Ps = Vs + 64*65;
    float* mrow = Ps + 64*65;       // 64
    float* lrow = mrow + 64;        // 64
    float* arow = lrow + 64;        // 64

    const int q0 = blockIdx.x * 64;
    const int h  = blockIdx.y;
    const int b  = blockIdx.z;
    const size_t head_off = (((size_t)b * Hn + h) * Sn) * DKn;
    const float* Q = g_q + head_off;
    const float* K = g_k + head_off;
    const float* V = g_v + head_off;

    const int tid = threadIdx.x;
    const int tx = tid & 15, ty = tid >> 4;

    for (int i = tid; i < 64*64; i += 256) {
        int r = i >> 6, d = i & 63;
        Qs[r*65 + d] = Q[(size_t)(q0 + r) * DKn + d];
    }
    if (tid < 64) { mrow[tid] = -INFINITY; lrow[tid] = 0.f; }
    float o[4][4] = {};
    __syncthreads();

    for (int k0 = 0; k0 < Sn; k0 += 64) {
        for (int i = tid; i < 64*64; i += 256) {
            int r = i >> 6, d = i & 63;
            Ks[r*65 + d] = K[(size_t)(k0 + r) * DKn + d];
            Vs[r*65 + d] = V[(size_t)(k0 + r) * DKn + d];
        }
        __syncthreads();

        // S = Q K^T * 1/sqrt(DK)
        float sacc[4][4] = {};
        #pragma unroll
        for (int d = 0; d < 64; d++) {
            float a[4], c[4];
            #pragma unroll
            for (int i = 0; i < 4; i++) a[i] = Qs[(ty*4 + i)*65 + d];
            #pragma unroll
            for (int j = 0; j < 4; j++) c[j] = Ks[(tx*4 + j)*65 + d];
            #pragma unroll
            for (int i = 0; i < 4; i++)
                #pragma unroll
                for (int j = 0; j < 4; j++)
                    sacc[i][j] = fmaf(a[i], c[j], sacc[i][j]);
        }
        #pragma unroll
        for (int j = 0; j < 4; j++) {
            const int key = k0 + tx*4 + j;
            const int mv = mask[b * Sn + key];
            #pragma unroll
            for (int i = 0; i < 4; i++) {
                float v = sacc[i][j] * 0.125f;
                if (mv == 0) v = -1e9f;
                Ps[(ty*4 + i)*65 + tx*4 + j] = v;
            }
        }
        __syncthreads();

        // online softmax per row (64 rows handled by 64 threads)
        if (tid < 64) {
            const int r = tid;
            float mx = -INFINITY;
            for (int c = 0; c < 64; c++) mx = fmaxf(mx, Ps[r*65 + c]);
            const float mold = mrow[r];
            const float mnew = fmaxf(mold, mx);
            const float al = __expf(mold - mnew);
            float sum = 0.f;
            for (int c = 0; c < 64; c++) {
                float p = __expf(Ps[r*65 + c] - mnew);
                Ps[r*65 + c] = p;
                sum += p;
            }
            lrow[r] = lrow[r] * al + sum;
            mrow[r] = mnew;
            arow[r] = al;
        }
        __syncthreads();

        // O = O*alpha + P V
        #pragma unroll
        for (int i = 0; i < 4; i++) {
            const float al = arow[ty*4 + i];
            #pragma unroll
            for (int j = 0; j < 4; j++) o[i][j] *= al;
        }
        #pragma unroll
        for (int kk = 0; kk < 64; kk++) {
            float p[4], v[4];
            #pragma unroll
            for (int i = 0; i < 4; i++) p[i] = Ps[(ty*4 + i)*65 + kk];
            #pragma unroll
            for (int j = 0; j < 4; j++) v[j] = Vs[kk*65 + tx*4 + j];
            #pragma unroll
            for (int i = 0; i < 4; i++)
                #pragma unroll
                for (int j = 0; j < 4; j++)
                    o[i][j] = fmaf(p[i], v[j], o[i][j]);
        }
        __syncthreads();
    }

    // write ctx[b, s, h*DK + dk]
    #pragma unroll
    for (int i = 0; i < 4; i++) {
        const int r = ty*4 + i;
        const float inv_l = 1.f / lrow[r];
        #pragma unroll
        for (int j = 0; j < 4; j++) {
            const int c = tx*4 + j;
            g_ctx[((size_t)b * Sn + (q0 + r)) * Dn + h * DKn + c] = o[i][j] * inv_l;
        }
    }
}

// ---------------- LayerNorm over D=512 ----------------
__global__ __launch_bounds__(256)
void ln_kernel(const float* __restrict__ in, const float* __restrict__ g,
               const float* __restrict__ beta, float* __restrict__ out)
{
    const int row = blockIdx.x;
    const float* x = in + (size_t)row * Dn;
    const int tid = threadIdx.x;

    float v0 = x[tid], v1 = x[tid + 256];
    float s = v0 + v1;
    __shared__ float red[8];
    __shared__ float mu_s, rs_s;
    #pragma unroll
    for (int o = 16; o; o >>= 1) s += __shfl_xor_sync(0xffffffffu, s, o);
    if ((tid & 31) == 0) red[tid >> 5] = s;
    __syncthreads();
    if (tid == 0) {
        float t = 0.f;
        #pragma unroll
        for (int i = 0; i < 8; i++) t += red[i];
        mu_s = t * (1.0f / Dn);
    }
    __syncthreads();
    const float mu = mu_s;
    const float d0 = v0 - mu, d1 = v1 - mu;
    float vs = d0*d0 + d1*d1;
    #pragma unroll
    for (int o = 16; o; o >>= 1) vs += __shfl_xor_sync(0xffffffffu, vs, o);
    if ((tid & 31) == 0) red[tid >> 5] = vs;
    __syncthreads();
    if (tid == 0) {
        float t = 0.f;
        #pragma unroll
        for (int i = 0; i < 8; i++) t += red[i];
        rs_s = rsqrtf(t * (1.0f / Dn) + 1e-5f);
    }
    __syncthreads();
    const float rs = rs_s;
    out[(size_t)row * Dn + tid]       = d0 * rs * g[tid]       + beta[tid];
    out[(size_t)row * Dn + tid + 256] = d1 * rs * g[tid + 256] + beta[tid + 256];
}

// ---------------- launch ----------------
extern "C" void kernel_launch(void* const* d_in, const int* in_sizes, int n_in,
                              void* d_out, int out_size)
{
    const float* x   = (const float*)d_in[0];
    const int*   msk = (const int*)  d_in[1];
    const float* wq  = (const float*)d_in[2];
    const float* wk  = (const float*)d_in[3];
    const float* wv  = (const float*)d_in[4];
    const float* wo  = (const float*)d_in[5];
    const float* w1  = (const float*)d_in[6];
    const float* b1  = (const float*)d_in[7];
    const float* w2  = (const float*)d_in[8];
    const float* b2  = (const float*)d_in[9];
    const float* g1  = (const float*)d_in[10];
    const float* be1 = (const float*)d_in[11];
    const float* g2  = (const float*)d_in[12];
    const float* be2 = (const float*)d_in[13];
    float* out = (float*)d_out;

    float *q, *k, *v, *ctx, *res1, *x1, *ff;
    cudaGetSymbolAddress((void**)&q,    g_q);
    cudaGetSymbolAddress((void**)&k,    g_k);
    cudaGetSymbolAddress((void**)&v,    g_v);
    cudaGetSymbolAddress((void**)&ctx,  g_ctx);
    cudaGetSymbolAddress((void**)&res1, g_res1);
    cudaGetSymbolAddress((void**)&x1,   g_x1);
    cudaGetSymbolAddress((void**)&ff,   g_ff);

    const dim3 blk(256);
    const dim3 g512(Dn/64, Mrows/64);     // (8,128)
    const dim3 gff1(DFFn/64, Mrows/64);   // (32,128)

    // QKV projections -> [B,H,S,DK]
    gemm_kernel<Dn, Dn, EPI_QKV><<<g512, blk>>>(x, wq, nullptr, nullptr, q);
    gemm_kernel<Dn, Dn, EPI_QKV><<<g512, blk>>>(x, wk, nullptr, nullptr, k);
    gemm_kernel<Dn, Dn, EPI_QKV><<<g512, blk>>>(x, wv, nullptr, nullptr, v);

    // attention
    const int smem = (4 * 64 * 65 + 3 * 64) * (int)sizeof(float); // 67328 B
    cudaFuncSetAttribute(attn_kernel, cudaFuncAttributeMaxDynamicSharedMemorySize, smem);
    attn_kernel<<<dim3(Sn/64, Hn, Bn), blk, smem>>>(msk);

    // attn_out projection + residual
    gemm_kernel<Dn, Dn, EPI_RES><<<g512, blk>>>(ctx, wo, nullptr, x, res1);
    // LN1
    ln_kernel<<<Mrows, blk>>>(res1, g1, be1, x1);
    // FFN
    gemm_kernel<DFFn, Dn, EPI_BIAS_RELU><<<gff1, blk>>>(x1, w1, b1, nullptr, ff);
    gemm_kernel<Dn, DFFn, EPI_BIAS_RES><<<g512, blk>>>(ff, w2, b2, x1, res1);
    // LN2 -> out
    ln_kernel<<<Mrows, blk>>>(res1, g2, be2, out);
}

// round 4
// speedup vs baseline: 1.1600x; 1.1600x over previous
#include <cuda_runtime.h>
#include <math.h>
#include <stdint.h>

#define Bn   2
#define Sn   4096
#define Dn   512
#define Hn   8
#define DKn  64
#define DFFn 2048
#define Mrows (Bn*Sn)   /* 8192 */

// ---------------- scratch (no allocs allowed) ----------------
__device__ float g_q[Bn*Hn*Sn*DKn];     // [B,H,S,DK]
__device__ float g_k[Bn*Hn*Sn*DKn];
__device__ float g_v[Bn*Hn*Sn*DKn];
__device__ float g_ctx[Mrows*Dn];       // [B,S,D]
__device__ float g_res1[Mrows*Dn];
__device__ float g_x1[Mrows*Dn];
__device__ float g_ff[Mrows*DFFn];

// ---------------- packed f32x2 helpers ----------------
typedef unsigned long long u64t;

__device__ __forceinline__ u64t pack2(float lo, float hi) {
    u64t r;
    asm("mov.b64 %0, {%1, %2};" : "=l"(r) : "f"(lo), "f"(hi));
    return r;
}
__device__ __forceinline__ void unpack2(u64t v, float& lo, float& hi) {
    asm("mov.b64 {%0, %1}, %2;" : "=f"(lo), "=f"(hi) : "l"(v));
}
__device__ __forceinline__ u64t fma2(u64t a, u64t b, u64t c) {
    u64t d;
    asm("fma.rn.f32x2 %0, %1, %2, %3;" : "=l"(d) : "l"(a), "l"(b), "l"(c));
    return d;
}
__device__ __forceinline__ u64t mul2(u64t a, u64t b) {
    u64t d;
    asm("mul.rn.f32x2 %0, %1, %2;" : "=l"(d) : "l"(a), "l"(b));
    return d;
}

// ---------------- GEMM: C[M,N] = A[M,K] @ W[K,N] + epilogue ----------------
// 128x128 block tile, BK=32, 256 threads, 8x8 microtile, f32x2 packed FMA.
#define EPI_QKV       0
#define EPI_RES       1
#define EPI_BIAS_RELU 2
#define EPI_BIAS_RES  3

template<int N, int K, int EPI>
__global__ __launch_bounds__(256, 2)
void gemm_kernel(const float* __restrict__ A, const float* __restrict__ W,
                 const float* __restrict__ bias, const float* __restrict__ res,
                 float* __restrict__ out)
{
    __shared__ float As[32][132];   // k-major A tile
    __shared__ float Bs[32][132];
    const int tid = threadIdx.x;
    const int tx = tid & 15, ty = tid >> 4;
    const int row0 = blockIdx.y * 128;
    const int col0 = blockIdx.x * 128;

    // A tile load: 2 threads/row, 16 floats each (4 float4 along K)
    const int ar  = tid >> 1;
    const int akc = (tid & 1) * 16;
    // B tile load: 8 threads/row, 16 floats each (4 float4 along N)
    const int bkk = tid >> 3;
    const int bnc = (tid & 7) * 16;

    u64t acc2[8][4];
    #pragma unroll
    for (int i = 0; i < 8; i++)
        #pragma unroll
        for (int jj = 0; jj < 4; jj++) acc2[i][jj] = 0ull;

    for (int k0 = 0; k0 < K; k0 += 32) {
        const float4* Ag = (const float4*)(A + (size_t)(row0 + ar) * K + k0 + akc);
        #pragma unroll
        for (int c = 0; c < 4; c++) {
            float4 v = Ag[c];
            As[akc + c*4 + 0][ar] = v.x;
            As[akc + c*4 + 1][ar] = v.y;
            As[akc + c*4 + 2][ar] = v.z;
            As[akc + c*4 + 3][ar] = v.w;
        }
        const float4* Bg = (const float4*)(W + (size_t)(k0 + bkk) * N + col0 + bnc);
        #pragma unroll
        for (int c = 0; c < 4; c++)
            *(float4*)&Bs[bkk][bnc + c*4] = Bg[c];
        __syncthreads();

        #pragma unroll 8
        for (int kk = 0; kk < 32; kk++) {
            float a[8];
            *(float4*)&a[0] = *(const float4*)&As[kk][ty*8];
            *(float4*)&a[4] = *(const float4*)&As[kk][ty*8 + 4];
            ulonglong2 b01 = *(const ulonglong2*)&Bs[kk][tx*8];
            ulonglong2 b23 = *(const ulonglong2*)&Bs[kk][tx*8 + 4];
            u64t bb[4] = {b01.x, b01.y, b23.x, b23.y};
            #pragma unroll
            for (int i = 0; i < 8; i++) {
                u64t ad = pack2(a[i], a[i]);
                #pragma unroll
                for (int jj = 0; jj < 4; jj++)
                    acc2[i][jj] = fma2(ad, bb[jj], acc2[i][jj]);
            }
        }
        __syncthreads();
    }

    // epilogue
    #pragma unroll
    for (int i = 0; i < 8; i++) {
        const int r  = row0 + ty*8 + i;
        const int c0 = col0 + tx*8;
        float cv[8];
        #pragma unroll
        for (int jj = 0; jj < 4; jj++) unpack2(acc2[i][jj], cv[2*jj], cv[2*jj+1]);

        if (EPI == EPI_QKV) {
            const int b = r >> 12, s = r & (Sn - 1);
            const int h = c0 >> 6, dk = c0 & 63;
            float* dst = out + (((size_t)b * Hn + h) * Sn + s) * DKn + dk;
            *(float4*)dst       = make_float4(cv[0], cv[1], cv[2], cv[3]);
            *(float4*)(dst + 4) = make_float4(cv[4], cv[5], cv[6], cv[7]);
        } else if (EPI == EPI_RES) {
            const float* rp = res + (size_t)r * N + c0;
            float4 r0 = *(const float4*)rp, r1 = *(const float4*)(rp + 4);
            float* dst = out + (size_t)r * N + c0;
            *(float4*)dst       = make_float4(cv[0]+r0.x, cv[1]+r0.y, cv[2]+r0.z, cv[3]+r0.w);
            *(float4*)(dst + 4) = make_float4(cv[4]+r1.x, cv[5]+r1.y, cv[6]+r1.z, cv[7]+r1.w);
        } else if (EPI == EPI_BIAS_RELU) {
            float4 b0 = *(const float4*)&bias[c0], b1 = *(const float4*)&bias[c0 + 4];
            float t0 = cv[0]+b0.x, t1 = cv[1]+b0.y, t2 = cv[2]+b0.z, t3 = cv[3]+b0.w;
            float t4 = cv[4]+b1.x, t5 = cv[5]+b1.y, t6 = cv[6]+b1.z, t7 = cv[7]+b1.w;
            float* dst = out + (size_t)r * N + c0;
            *(float4*)dst       = make_float4(fmaxf(t0,0.f), fmaxf(t1,0.f), fmaxf(t2,0.f), fmaxf(t3,0.f));
            *(float4*)(dst + 4) = make_float4(fmaxf(t4,0.f), fmaxf(t5,0.f), fmaxf(t6,0.f), fmaxf(t7,0.f));
        } else { // EPI_BIAS_RES
            float4 b0 = *(const float4*)&bias[c0], b1 = *(const float4*)&bias[c0 + 4];
            const float* rp = res + (size_t)r * N + c0;
            float4 r0 = *(const float4*)rp, r1 = *(const float4*)(rp + 4);
            float* dst = out + (size_t)r * N + c0;
            *(float4*)dst       = make_float4(cv[0]+b0.x+r0.x, cv[1]+b0.y+r0.y, cv[2]+b0.z+r0.z, cv[3]+b0.w+r0.w);
            *(float4*)(dst + 4) = make_float4(cv[4]+b1.x+r1.x, cv[5]+b1.y+r1.y, cv[6]+b1.z+r1.z, cv[7]+b1.w+r1.w);
        }
    }
}

// ---------------- Flash attention (fp32, f32x2, 128q x 128k tiles) ----------------
// grid (S/128, H, B), 256 threads. Thread = 8 query rows x 8 key cols (S),
// and 8 rows x 4 dk cols (O).
__global__ __launch_bounds__(256, 1)
void attn_kernel(const int* __restrict__ mask)
{
    extern __shared__ float sm[];
    float* Qs = sm;                  // [64][132]  (d-major)
    float* Ks = Qs + 64*132;         // [64][132]  (d-major)
    float* Vs = Ks + 64*132;         // [128][68]  (key-major)
    float* Pr = Vs + 128*68;         // [128][132] (row-major P)

    const int q0 = blockIdx.x * 128;
    const int h  = blockIdx.y;
    const int b  = blockIdx.z;
    const size_t head_off = (((size_t)b * Hn + h) * Sn) * DKn;
    const float* Q = g_q + head_off;
    const float* K = g_k + head_off;
    const float* V = g_v + head_off;

    const int tid = threadIdx.x;
    const int tx = tid & 15, ty = tid >> 4;
    const int lr = tid >> 1;             // 0..127 (loader row)
    const int ldc = (tid & 1) * 32;      // 0 or 32 (loader d-chunk)

    // load Q transposed into Qs[d][r]
    {
        const float4* Qg = (const float4*)(Q + (size_t)(q0 + lr) * DKn + ldc);
        #pragma unroll
        for (int c = 0; c < 8; c++) {
            float4 v = Qg[c];
            Qs[(ldc + c*4 + 0)*132 + lr] = v.x;
            Qs[(ldc + c*4 + 1)*132 + lr] = v.y;
            Qs[(ldc + c*4 + 2)*132 + lr] = v.z;
            Qs[(ldc + c*4 + 3)*132 + lr] = v.w;
        }
    }

    u64t o2[8][2];
    float mrun[8], lrun[8];
    #pragma unroll
    for (int i = 0; i < 8; i++) {
        o2[i][0] = 0ull; o2[i][1] = 0ull;
        mrun[i] = -INFINITY; lrun[i] = 0.f;
    }
    __syncthreads();

    for (int k0 = 0; k0 < Sn; k0 += 128) {
        // load K transposed (Ks[d][c]) and V natural (Vs[c][d])
        {
            const float4* Kg = (const float4*)(K + (size_t)(k0 + lr) * DKn + ldc);
            const float4* Vg = (const float4*)(V + (size_t)(k0 + lr) * DKn + ldc);
            #pragma unroll
            for (int c = 0; c < 8; c++) {
                float4 kv = Kg[c];
                Ks[(ldc + c*4 + 0)*132 + lr] = kv.x;
                Ks[(ldc + c*4 + 1)*132 + lr] = kv.y;
                Ks[(ldc + c*4 + 2)*132 + lr] = kv.z;
                Ks[(ldc + c*4 + 3)*132 + lr] = kv.w;
                *(float4*)&Vs[lr*68 + ldc + c*4] = Vg[c];
            }
        }
        __syncthreads();

        // S = Q K^T (packed along key cols)
        u64t s2[8][4];
        #pragma unroll
        for (int i = 0; i < 8; i++)
            #pragma unroll
            for (int jj = 0; jj < 4; jj++) s2[i][jj] = 0ull;

        #pragma unroll 8
        for (int d = 0; d < 64; d++) {
            float a[8];
            *(float4*)&a[0] = *(const float4*)&Qs[d*132 + ty*8];
            *(float4*)&a[4] = *(const float4*)&Qs[d*132 + ty*8 + 4];
            ulonglong2 k01 = *(const ulonglong2*)&Ks[d*132 + tx*8];
            ulonglong2 k23 = *(const ulonglong2*)&Ks[d*132 + tx*8 + 4];
            u64t kb[4] = {k01.x, k01.y, k23.x, k23.y};
            #pragma unroll
            for (int i = 0; i < 8; i++) {
                u64t ad = pack2(a[i], a[i]);
                #pragma unroll
                for (int jj = 0; jj < 4; jj++)
                    s2[i][jj] = fma2(ad, kb[jj], s2[i][jj]);
            }
        }

        // unpack, scale, mask
        float p[8][8];
        #pragma unroll
        for (int i = 0; i < 8; i++)
            #pragma unroll
            for (int jj = 0; jj < 4; jj++)
                unpack2(s2[i][jj], p[i][2*jj], p[i][2*jj+1]);

        int mv[8];
        #pragma unroll
        for (int j = 0; j < 8; j++) mv[j] = mask[b * Sn + k0 + tx*8 + j];
        #pragma unroll
        for (int i = 0; i < 8; i++)
            #pragma unroll
            for (int j = 0; j < 8; j++) {
                float v = p[i][j] * 0.125f;
                p[i][j] = (mv[j] == 0) ? -1e9f : v;
            }

        // online softmax: rows live in 16-lane groups (same ty)
        #pragma unroll
        for (int i = 0; i < 8; i++) {
            float mx = p[i][0];
            #pragma unroll
            for (int j = 1; j < 8; j++) mx = fmaxf(mx, p[i][j]);
            #pragma unroll
            for (int off = 8; off; off >>= 1)
                mx = fmaxf(mx, __shfl_xor_sync(0xffffffffu, mx, off));
            const float mnew = fmaxf(mrun[i], mx);
            const float al = __expf(mrun[i] - mnew);
            mrun[i] = mnew;
            float sum = 0.f;
            #pragma unroll
            for (int j = 0; j < 8; j++) {
                p[i][j] = __expf(p[i][j] - mnew);
                sum += p[i][j];
            }
            #pragma unroll
            for (int off = 8; off; off >>= 1)
                sum += __shfl_xor_sync(0xffffffffu, sum, off);
            lrun[i] = lrun[i] * al + sum;
            const u64t alp = pack2(al, al);
            o2[i][0] = mul2(alp, o2[i][0]);
            o2[i][1] = mul2(alp, o2[i][1]);
        }

        // store P row-major (float4 stores)
        #pragma unroll
        for (int i = 0; i < 8; i++) {
            float* pd = &Pr[(ty*8 + i)*132 + tx*8];
            *(float4*)pd       = make_float4(p[i][0], p[i][1], p[i][2], p[i][3]);
            *(float4*)(pd + 4) = make_float4(p[i][4], p[i][5], p[i][6], p[i][7]);
        }
        __syncthreads();

        // O += P V   (packed along dk)
        #pragma unroll 4
        for (int kk = 0; kk < 128; kk++) {
            ulonglong2 v2 = *(const ulonglong2*)&Vs[kk*68 + tx*4];
            #pragma unroll
            for (int i = 0; i < 8; i++) {
                const float pv = Pr[(ty*8 + i)*132 + kk];
                const u64t pd = pack2(pv, pv);
                o2[i][0] = fma2(pd, v2.x, o2[i][0]);
                o2[i][1] = fma2(pd, v2.y, o2[i][1]);
            }
        }
        __syncthreads();
    }

    // write ctx[b, s, h*64 + dk]
    #pragma unroll
    for (int i = 0; i < 8; i++) {
        const float inv = 1.f / lrun[i];
        float ov[4];
        unpack2(o2[i][0], ov[0], ov[1]);
        unpack2(o2[i][1], ov[2], ov[3]);
        const int r = q0 + ty*8 + i;
        float* dst = g_ctx + ((size_t)b * Sn + r) * Dn + h * DKn + tx*4;
        *(float4*)dst = make_float4(ov[0]*inv, ov[1]*inv, ov[2]*inv, ov[3]*inv);
    }
}

// ---------------- LayerNorm over D=512 ----------------
__global__ __launch_bounds__(256)
void ln_kernel(const float* __restrict__ in, const float* __restrict__ g,
               const float* __restrict__ beta, float* __restrict__ out)
{
    const int row = blockIdx.x;
    const float* x = in + (size_t)row * Dn;
    const int tid = threadIdx.x;

    float v0 = x[tid], v1 = x[tid + 256];
    float s = v0 + v1;
    __shared__ float red[8];
    __shared__ float mu_s, rs_s;
    #pragma unroll
    for (int o = 16; o; o >>= 1) s += __shfl_xor_sync(0xffffffffu, s, o);
    if ((tid & 31) == 0) red[tid >> 5] = s;
    __syncthreads();
    if (tid == 0) {
        float t = 0.f;
        #pragma unroll
        for (int i = 0; i < 8; i++) t += red[i];
        mu_s = t * (1.0f / Dn);
    }
    __syncthreads();
    const float mu = mu_s;
    const float d0 = v0 - mu, d1 = v1 - mu;
    float vs = d0*d0 + d1*d1;
    #pragma unroll
    for (int o = 16; o; o >>= 1) vs += __shfl_xor_sync(0xffffffffu, vs, o);
    if ((tid & 31) == 0) red[tid >> 5] = vs;
    __syncthreads();
    if (tid == 0) {
        float t = 0.f;
        #pragma unroll
        for (int i = 0; i < 8; i++) t += red[i];
        rs_s = rsqrtf(t * (1.0f / Dn) + 1e-5f);
    }
    __syncthreads();
    const float rs = rs_s;
    out[(size_t)row * Dn + tid]       = d0 * rs * g[tid]       + beta[tid];
    out[(size_t)row * Dn + tid + 256] = d1 * rs * g[tid + 256] + beta[tid + 256];
}

// ---------------- launch ----------------
extern "C" void kernel_launch(void* const* d_in, const int* in_sizes, int n_in,
                              void* d_out, int out_size)
{
    const float* x   = (const float*)d_in[0];
    const int*   msk = (const int*)  d_in[1];
    const float* wq  = (const float*)d_in[2];
    const float* wk  = (const float*)d_in[3];
    const float* wv  = (const float*)d_in[4];
    const float* wo  = (const float*)d_in[5];
    const float* w1  = (const float*)d_in[6];
    const float* b1  = (const float*)d_in[7];
    const float* w2  = (const float*)d_in[8];
    const float* b2  = (const float*)d_in[9];
    const float* g1  = (const float*)d_in[10];
    const float* be1 = (const float*)d_in[11];
    const float* g2  = (const float*)d_in[12];
    const float* be2 = (const float*)d_in[13];
    float* out = (float*)d_out;

    float *q, *k, *v, *ctx, *res1, *x1, *ff;
    cudaGetSymbolAddress((void**)&q,    g_q);
    cudaGetSymbolAddress((void**)&k,    g_k);
    cudaGetSymbolAddress((void**)&v,    g_v);
    cudaGetSymbolAddress((void**)&ctx,  g_ctx);
    cudaGetSymbolAddress((void**)&res1, g_res1);
    cudaGetSymbolAddress((void**)&x1,   g_x1);
    cudaGetSymbolAddress((void**)&ff,   g_ff);

    const dim3 blk(256);
    const dim3 g512(Dn/128,  Mrows/128);   // (4,64)
    const dim3 gff1(DFFn/128, Mrows/128);  // (16,64)

    // QKV projections -> [B,H,S,DK]
    gemm_kernel<Dn, Dn, EPI_QKV><<<g512, blk>>>(x, wq, nullptr, nullptr, q);
    gemm_kernel<Dn, Dn, EPI_QKV><<<g512, blk>>>(x, wk, nullptr, nullptr, k);
    gemm_kernel<Dn, Dn, EPI_QKV><<<g512, blk>>>(x, wv, nullptr, nullptr, v);

    // attention
    const int smem = (64*132 + 64*132 + 128*68 + 128*132) * (int)sizeof(float); // 169984
    cudaFuncSetAttribute(attn_kernel, cudaFuncAttributeMaxDynamicSharedMemorySize, smem);
    attn_kernel<<<dim3(Sn/128, Hn, Bn), blk, smem>>>(msk);

    // attn_out projection + residual
    gemm_kernel<Dn, Dn, EPI_RES><<<g512, blk>>>(ctx, wo, nullptr, x, res1);
    // LN1
    ln_kernel<<<Mrows, blk>>>(res1, g1, be1, x1);
    // FFN
    gemm_kernel<DFFn, Dn, EPI_BIAS_RELU><<<gff1, blk>>>(x1, w1, b1, nullptr, ff);
    gemm_kernel<Dn, DFFn, EPI_BIAS_RES><<<g512, blk>>>(ff, w2, b2, x1, res1);
    // LN2 -> out
    ln_kernel<<<Mrows, blk>>>(res1, g2, be2, out);
}